// round 2
// baseline (speedup 1.0000x reference)
#include <cuda_runtime.h>

#define BB 256
#define TT 4096
#define DD 3
#define UU 8
#define SIGD 21
#define CHUNK 16   // TT / 256 threads

// Scratch: per (b,t,u): {z_i_pre, z_c_pre, z_o_pre, f}  (biases folded)
__device__ float4 g_G[(size_t)BB * TT * UU];

__device__ __forceinline__ float fsig(float x) {
    float e = __expf(-x);
    return __fdividef(1.0f, 1.0f + e);
}
__device__ __forceinline__ float ftanh(float x) {
    float e = __expf(-2.0f * x);
    return __fdividef(2.0f, 1.0f + e) - 1.0f;
}

// ---------------------------------------------------------------------------
// Kernel A: signature scan + forget gate + input projection (parallel B x T)
// ---------------------------------------------------------------------------
__global__ __launch_bounds__(256) void sig_kernel(
    const float* __restrict__ inp,   // (B,T,3)
    const float* __restrict__ Wi,    // (3,24)
    const float* __restrict__ Wf,    // (21,8)
    const float* __restrict__ bias)  // (32) = [b_i, b_f, b_c, b_o]
{
    __shared__ float sh[2][256][20];
    __shared__ float swf[SIGD * UU];   // 168
    __shared__ float swi[DD * 3 * UU]; // 72
    __shared__ float sb[4 * UU];       // 32

    const int b = blockIdx.x;
    const int j = threadIdx.x;
    if (j < SIGD * UU)   swf[j] = Wf[j];
    if (j < DD * 3 * UU) swi[j] = Wi[j];
    if (j < 4 * UU)      sb[j]  = bias[j];

    const float dt = 1.0f / (float)(TT - 1);
    const int t0 = j * CHUNK;
    const float* ip = inp + ((size_t)b * TT + t0) * DD;

    // ---- pass 1: local chunk signature (diffs t0+1 .. t0+16) ----
    float L1[4] = {0.f, 0.f, 0.f, 0.f};
    float L2[16] = {0.f};
    {
        float p0 = ip[0], p1 = ip[1], p2 = ip[2];
        #pragma unroll
        for (int s = 1; s <= CHUNK; s++) {
            int tg = t0 + s;
            if (tg <= TT - 1) {
                float c0 = ip[s * DD + 0], c1 = ip[s * DD + 1], c2 = ip[s * DD + 2];
                float dx[4] = {dt, c0 - p0, c1 - p1, c2 - p2};
                #pragma unroll
                for (int p = 0; p < 4; p++) {
                    float a = L1[p] + 0.5f * dx[p];
                    #pragma unroll
                    for (int q = 0; q < 4; q++)
                        L2[p * 4 + q] += a * dx[q];
                }
                #pragma unroll
                for (int p = 0; p < 4; p++) L1[p] += dx[p];
                p0 = c0; p1 = c1; p2 = c2;
            }
        }
    }

    // ---- inclusive Hillis-Steele scan of Chen states over 256 chunks ----
    #pragma unroll
    for (int p = 0; p < 4; p++)  sh[0][j][p] = L1[p];
    #pragma unroll
    for (int p = 0; p < 16; p++) sh[0][j][4 + p] = L2[p];
    __syncthreads();

    int cur = 0;
    for (int ofs = 1; ofs < 256; ofs <<= 1) {
        float v[20];
        #pragma unroll
        for (int p = 0; p < 20; p++) v[p] = sh[cur][j][p];
        if (j >= ofs) {
            const float* a = sh[cur][j - ofs];  // earlier aggregate
            float o[20];
            #pragma unroll
            for (int p = 0; p < 4; p++) o[p] = a[p] + v[p];
            #pragma unroll
            for (int p = 0; p < 4; p++)
                #pragma unroll
                for (int q = 0; q < 4; q++)
                    o[4 + p * 4 + q] = a[4 + p * 4 + q] + v[4 + p * 4 + q] + a[p] * v[q];
            #pragma unroll
            for (int p = 0; p < 20; p++) v[p] = o[p];
        }
        #pragma unroll
        for (int p = 0; p < 20; p++) sh[1 - cur][j][p] = v[p];
        __syncthreads();
        cur = 1 - cur;
    }

    // exclusive prefix = signature of path up to time t0
    if (j == 0) {
        #pragma unroll
        for (int p = 0; p < 4; p++)  L1[p] = 0.f;
        #pragma unroll
        for (int p = 0; p < 16; p++) L2[p] = 0.f;
    } else {
        #pragma unroll
        for (int p = 0; p < 4; p++)  L1[p] = sh[cur][j - 1][p];
        #pragma unroll
        for (int p = 0; p < 16; p++) L2[p] = sh[cur][j - 1][4 + p];
    }

    // ---- pass 2: per-timestep signature, forget gate, input projection ----
    float4* Gp = g_G + ((size_t)b * TT) * UU;
    float p0 = ip[0], p1 = ip[1], p2 = ip[2];
    float x0 = p0, x1 = p1, x2 = p2;

    #pragma unroll
    for (int s = 0; s < CHUNK; s++) {
        const int t = t0 + s;
        if (s > 0) {
            float c0 = ip[s * DD + 0], c1 = ip[s * DD + 1], c2 = ip[s * DD + 2];
            float dx[4] = {dt, c0 - p0, c1 - p1, c2 - p2};
            #pragma unroll
            for (int p = 0; p < 4; p++) {
                float a = L1[p] + 0.5f * dx[p];
                #pragma unroll
                for (int q = 0; q < 4; q++)
                    L2[p * 4 + q] += a * dx[q];
            }
            #pragma unroll
            for (int p = 0; p < 4; p++) L1[p] += dx[p];
            p0 = c0; p1 = c1; p2 = c2;
            x0 = c0; x1 = c1; x2 = c2;
        }
        float scale = (t == 0) ? 1.0f : (float)(TT - 1) / (float)t;

        #pragma unroll
        for (int u = 0; u < UU; u++) {
            // forget logit: sig_norm . Wf[:,u] + b_f[u]
            float acc = swf[u];  // constant term (m=0)
            #pragma unroll
            for (int p = 0; p < 4; p++)  acc += L1[p] * swf[(1 + p) * UU + u];
            #pragma unroll
            for (int p = 0; p < 16; p++) acc += L2[p] * swf[(5 + p) * UU + u];
            float f = fsig(scale * acc + sb[UU + u]);

            float zi = x0 * swi[u]          + x1 * swi[24 + u]          + x2 * swi[48 + u]          + sb[u];
            float zc = x0 * swi[8 + u]      + x1 * swi[24 + 8 + u]      + x2 * swi[48 + 8 + u]      + sb[2 * UU + u];
            float zo = x0 * swi[16 + u]     + x1 * swi[24 + 16 + u]     + x2 * swi[48 + 16 + u]     + sb[3 * UU + u];

            Gp[(size_t)t * UU + u] = make_float4(zi, zc, zo, f);
        }
    }
}

// ---------------------------------------------------------------------------
// Kernel B: sequential LSTM recurrence. Warp = 4 batches x 8 lanes (lane=unit)
// ---------------------------------------------------------------------------
__global__ __launch_bounds__(32) void lstm_kernel(
    const float* __restrict__ Wr,  // (8,24)
    float* __restrict__ out)       // (B,T,8)
{
    const int lane = threadIdx.x;
    const int g = lane >> 3;
    const int u = lane & 7;
    const int b = blockIdx.x * 4 + g;

    float wi[8], wc[8], wo[8];
    #pragma unroll
    for (int k = 0; k < 8; k++) {
        wi[k] = Wr[k * 24 + u];
        wc[k] = Wr[k * 24 + 8 + u];
        wo[k] = Wr[k * 24 + 16 + u];
    }

    const float4* Gp = g_G + ((size_t)b * TT) * UU + u;
    float* op = out + ((size_t)b * TT) * UU + u;

    float hk[8];
    #pragma unroll
    for (int k = 0; k < 8; k++) hk[k] = 0.0f;
    float c = 0.0f;

    const int PF = 8;  // prefetch depth (steps)
    float4 buf[PF];
    #pragma unroll
    for (int p = 0; p < PF; p++) buf[p] = Gp[(size_t)p * UU];

    for (int t = 0; t < TT; t += PF) {
        #pragma unroll
        for (int k2 = 0; k2 < PF; k2++) {
            float4 v = buf[k2];
            int tn = t + k2 + PF;
            if (tn > TT - 1) tn = TT - 1;
            buf[k2] = Gp[(size_t)tn * UU];   // prefetch, off critical path

            float zi = v.x, zc = v.y, zo = v.z, f = v.w;
            #pragma unroll
            for (int k = 0; k < 8; k++) {
                zi += hk[k] * wi[k];
                zc += hk[k] * wc[k];
                zo += hk[k] * wo[k];
            }
            float i  = fsig(zi);
            float cc = ftanh(zc);
            float o  = fsig(zo);
            c = f * c + i * cc;
            float tc = ftanh(c);
            float h = o * tc;

            op[(size_t)(t + k2) * UU] = h;

            #pragma unroll
            for (int k = 0; k < 8; k++)
                hk[k] = __shfl_sync(0xffffffffu, h, k, 8);
        }
    }
}

// ---------------------------------------------------------------------------
extern "C" void kernel_launch(void* const* d_in, const int* in_sizes, int n_in,
                              void* d_out, int out_size) {
    const float* inputs = (const float*)d_in[0];  // (256,4096,3)
    const float* Wi     = (const float*)d_in[1];  // (3,24)
    const float* Wr     = (const float*)d_in[2];  // (8,24)
    const float* Wf     = (const float*)d_in[3];  // (21,8)
    const float* bias   = (const float*)d_in[4];  // (32)
    float* out = (float*)d_out;                   // (256,4096,8) f32

    sig_kernel<<<BB, 256>>>(inputs, Wi, Wf, bias);
    lstm_kernel<<<BB / 4, 32>>>(Wr, out);
}